// round 12
// baseline (speedup 1.0000x reference)
#include <cuda_runtime.h>
#include <cstdint>

#define BB 4
#define CC 256
#define TT 4096
#define CQ 32

// ---------------------------------------------------------------------------
// Scratch (allocation-free: __device__ globals)
// ---------------------------------------------------------------------------
__device__ float g_qs[(size_t)BB * TT * 64];    // [B*T][64]: 0-31 q_hi(tf32), 32-63 q_lo
__device__ float g_ks[(size_t)BB * TT * 64];    // [B*T][64]: k_hi | k_lo
__device__ float g_v[(size_t)BB * CC * TT];     // [B, C, T], tf32-rounded
__device__ float g_attn[(size_t)BB * TT * TT];  // [B, T, T]: tf32-rounded exp(S)
__device__ float g_partZ[(size_t)BB * TT * 32]; // per-row per-s-tile partial sums
__device__ float g_Whi[384 * 256];              // stacked W (q|k|v|pad), tf32 hi
__device__ float g_Wlo[384 * 256];              // residual lo (rows 320-383 zero)
__device__ float g_bias[384];

// ---------------------------------------------------------------------------
// Helpers (target-agnostic PTX only: mma.sync + cp.async, sm_80+ baseline)
// ---------------------------------------------------------------------------
__device__ __forceinline__ uint32_t smem_to_u32(const void* p) {
    uint32_t a;
    asm("{ .reg .u64 t; cvta.to.shared.u64 t, %1; cvt.u32.u64 %0, t; }" : "=r"(a) : "l"(p));
    return a;
}
__device__ __forceinline__ float tf32_rna(float x) {
    float r;
    asm("cvt.rna.tf32.f32 %0, %1;" : "=f"(r) : "f"(x));
    return r;
}
__device__ __forceinline__ void mma_tf32(float* c, const uint32_t* a, const uint32_t* b) {
    asm volatile(
        "mma.sync.aligned.m16n8k8.row.col.f32.tf32.tf32.f32 "
        "{%0,%1,%2,%3}, {%4,%5,%6,%7}, {%8,%9}, {%0,%1,%2,%3};"
        : "+f"(c[0]), "+f"(c[1]), "+f"(c[2]), "+f"(c[3])
        : "r"(a[0]), "r"(a[1]), "r"(a[2]), "r"(a[3]), "r"(b[0]), "r"(b[1]));
}
__device__ __forceinline__ void cp_async16(uint32_t dst, const void* src) {
    asm volatile("cp.async.cg.shared.global [%0], [%1], 16;" :: "r"(dst), "l"(src));
}
#define CP_COMMIT() asm volatile("cp.async.commit_group;" ::: "memory")
#define CP_WAIT(n)  asm volatile("cp.async.wait_group %0;" :: "n"(n) : "memory")

// ---------------------------------------------------------------------------
// Kernel 0: split stacked weights into tf32 hi/lo + gather bias.
// Row layout: 0-31 = Wq, 32-63 = Wk, 64-319 = Wv, 320-383 = zero padding.
// ---------------------------------------------------------------------------
__global__ __launch_bounds__(256) void wsplit_kernel(
    const float* __restrict__ Wq, const float* __restrict__ bq,
    const float* __restrict__ Wk, const float* __restrict__ bk,
    const float* __restrict__ Wv, const float* __restrict__ bv)
{
    int i = blockIdx.x * 256 + threadIdx.x;                 // < 384*256
    int row = i >> 8, c = i & 255;
    float w = 0.f;
    if (row < 32)       w = Wq[row * 256 + c];
    else if (row < 64)  w = Wk[(row - 32) * 256 + c];
    else if (row < 320) w = Wv[(row - 64) * 256 + c];
    float hi = tf32_rna(w);
    g_Whi[i] = hi;
    g_Wlo[i] = w - hi;
    if (i < 384) {
        float bb = 0.f;
        if (i < 32)       bb = bq[i];
        else if (i < 64)  bb = bk[i - 32];
        else if (i < 320) bb = bv[i - 64];
        g_bias[i] = bb;
    }
}

// ---------------------------------------------------------------------------
// Kernel 1: projections via mma.sync tf32.
// CTA: 128 stacked-rows x 128 t, K=256 in 8 chunks of 32.
// M-tile 0 (contains q,k rows): 3-pass exact split. Tiles 1,2 (pure v): 1 pass.
// ---------------------------------------------------------------------------
static constexpr int PJ_WS = 36;                            // W smem k-stride
static constexpr int PJ_XS = 132;                            // X smem t-stride
static constexpr int PJ_WH = 0;                             // float offsets
static constexpr int PJ_WL = PJ_WH + 128 * PJ_WS;
static constexpr int PJ_XH = PJ_WL + 128 * PJ_WS;
static constexpr int PJ_XL = PJ_XH + 32 * PJ_XS;
static constexpr int SMEM_PJ = (PJ_XL + 32 * PJ_XS) * 4;    // 70656 B

__global__ __launch_bounds__(256, 2) void proj_kernel(const float* __restrict__ x)
{
    extern __shared__ float sm[];
    int tid = threadIdx.x;
    int b = blockIdx.z, mBase = blockIdx.y << 7, tBase = blockIdx.x << 7;
    int passes = (blockIdx.y == 0) ? 3 : 1;

    int lane = tid & 31, wid = tid >> 5, g = lane >> 2, t4 = lane & 3;
    int m0 = (wid >> 2) * 64, n0 = (wid & 3) * 32;

    float acc[4][4][4] = {};

    for (int ch = 0; ch < 8; ch++) {
        __syncthreads();
        // W hi/lo tiles: 128 rows x 32 k
        for (int i = tid; i < 1024; i += 256) {
            int r = i >> 3, c4 = i & 7;
            size_t gsrc = (size_t)(mBase + r) * 256 + ch * 32 + c4 * 4;
            *(float4*)(sm + PJ_WH + r * PJ_WS + c4 * 4) = *(const float4*)(g_Whi + gsrc);
            *(float4*)(sm + PJ_WL + r * PJ_WS + c4 * 4) = *(const float4*)(g_Wlo + gsrc);
        }
        // X tile: 32 c x 128 t, split hi/lo on the fly
        for (int i = tid; i < 1024; i += 256) {
            int cl = i >> 5, tl = i & 31;
            float4 xv = *(const float4*)(x + ((size_t)(b * CC + ch * 32 + cl)) * TT + tBase + tl * 4);
            float4 h = make_float4(tf32_rna(xv.x), tf32_rna(xv.y), tf32_rna(xv.z), tf32_rna(xv.w));
            float4 l = make_float4(xv.x - h.x, xv.y - h.y, xv.z - h.z, xv.w - h.w);
            *(float4*)(sm + PJ_XH + cl * PJ_XS + tl * 4) = h;
            *(float4*)(sm + PJ_XL + cl * PJ_XS + tl * 4) = l;
        }
        __syncthreads();

        const uint32_t* Wh = (const uint32_t*)(sm + PJ_WH);
        const uint32_t* Wl = (const uint32_t*)(sm + PJ_WL);
        const uint32_t* Xh = (const uint32_t*)(sm + PJ_XH);
        const uint32_t* Xl = (const uint32_t*)(sm + PJ_XL);

        for (int p = 0; p < passes; p++) {
            const uint32_t* Aw = (p == 2) ? Wl : Wh;
            const uint32_t* Bx = (p == 1) ? Xl : Xh;
#pragma unroll
            for (int kk = 0; kk < 4; kk++) {
                int ka = kk * 8 + t4;
                uint32_t a[4][4], bf[4][2];
#pragma unroll
                for (int mt = 0; mt < 4; mt++) {
                    int r = m0 + mt * 16 + g;
                    a[mt][0] = Aw[r * PJ_WS + ka];
                    a[mt][1] = Aw[(r + 8) * PJ_WS + ka];
                    a[mt][2] = Aw[r * PJ_WS + ka + 4];
                    a[mt][3] = Aw[(r + 8) * PJ_WS + ka + 4];
                }
#pragma unroll
                for (int nt = 0; nt < 4; nt++) {
                    int s = n0 + nt * 8 + g;
                    bf[nt][0] = Bx[ka * PJ_XS + s];
                    bf[nt][1] = Bx[(ka + 4) * PJ_XS + s];
                }
#pragma unroll
                for (int mt = 0; mt < 4; mt++)
#pragma unroll
                    for (int nt = 0; nt < 4; nt++)
                        mma_tf32(acc[mt][nt], a[mt], bf[nt]);
            }
        }
    }

    // Epilogue: route rows to q(split) / k(split) / v(tf32). Rows >= 320 are
    // padding (skip). 320 is 16-aligned so branches stay warp-uniform.
#pragma unroll
    for (int mt = 0; mt < 4; mt++)
#pragma unroll
        for (int nt = 0; nt < 4; nt++) {
#pragma unroll
            for (int half = 0; half < 2; half++) {
                int grow = mBase + m0 + mt * 16 + g + half * 8;
                int tcol = tBase + n0 + nt * 8 + 2 * t4;
                float v0 = acc[mt][nt][half * 2 + 0] + g_bias[grow];
                float v1 = acc[mt][nt][half * 2 + 1] + g_bias[grow];
                if (grow < 64) {
                    float* base = (grow < 32) ? g_qs : g_ks;
                    int r = grow & 31;
                    float h0 = tf32_rna(v0), h1 = tf32_rna(v1);
                    size_t r0 = ((size_t)b * TT + tcol) * 64;
                    size_t r1 = ((size_t)b * TT + tcol + 1) * 64;
                    base[r0 + r] = h0; base[r0 + 32 + r] = v0 - h0;
                    base[r1 + r] = h1; base[r1 + 32 + r] = v1 - h1;
                } else if (grow < 320) {
                    size_t o = ((size_t)(b * CC + grow - 64)) * TT + tcol;
                    *(float2*)(g_v + o) = make_float2(tf32_rna(v0), tf32_rna(v1));
                }
            }
        }
}

// ---------------------------------------------------------------------------
// Kernel 2: scores + exp, via mma.sync tf32 (3-pass split: hh, hl, lh).
// CTA: 128 t x 128 s. Writes tf32(exp(S)) to g_attn, partial row sums to g_partZ.
// (Unchanged this round — pv is the single-variable experiment.)
// ---------------------------------------------------------------------------
static constexpr int SC_STRIDE = 68;
static constexpr int SMEM_SC = 2 * 128 * SC_STRIDE * 4;     // 69632 B

__global__ __launch_bounds__(256, 2) void scores_kernel()
{
    extern __shared__ float sm[];
    __shared__ float rsum[128][4];
    float* Qs = sm;
    float* Ks = sm + 128 * SC_STRIDE;
    int tid = threadIdx.x;
    int b = blockIdx.z, tBase = blockIdx.y << 7, sBase = blockIdx.x << 7;

    const float* qsrc = g_qs + ((size_t)b * TT + tBase) * 64;
    const float* ksrc = g_ks + ((size_t)b * TT + sBase) * 64;
    for (int i = tid; i < 2048; i += 256) {
        int r = i >> 4, c4 = i & 15;
        *(float4*)(Qs + r * SC_STRIDE + c4 * 4) = *(const float4*)(qsrc + r * 64 + c4 * 4);
        *(float4*)(Ks + r * SC_STRIDE + c4 * 4) = *(const float4*)(ksrc + r * 64 + c4 * 4);
    }
    __syncthreads();

    int lane = tid & 31, wid = tid >> 5, g = lane >> 2, t4 = lane & 3;
    int m0 = (wid >> 2) * 64, n0 = (wid & 3) * 32;

    float acc[4][4][4] = {};
    const uint32_t* Q32 = (const uint32_t*)Qs;
    const uint32_t* K32 = (const uint32_t*)Ks;

    const int amap[3] = {0, 0, 32};                         // (qh,kh)(qh,kl)(ql,kh)
    const int bmap[3] = {0, 32, 0};
#pragma unroll
    for (int p = 0; p < 3; p++) {
#pragma unroll
        for (int kk = 0; kk < 4; kk++) {
            int ka = amap[p] + kk * 8 + t4;
            int kb = bmap[p] + kk * 8 + t4;
            uint32_t a[4][4], bf[4][2];
#pragma unroll
            for (int mt = 0; mt < 4; mt++) {
                int r = m0 + mt * 16 + g;
                a[mt][0] = Q32[r * SC_STRIDE + ka];
                a[mt][1] = Q32[(r + 8) * SC_STRIDE + ka];
                a[mt][2] = Q32[r * SC_STRIDE + ka + 4];
                a[mt][3] = Q32[(r + 8) * SC_STRIDE + ka + 4];
            }
#pragma unroll
            for (int nt = 0; nt < 4; nt++) {
                int s = n0 + nt * 8 + g;
                bf[nt][0] = K32[s * SC_STRIDE + kb];
                bf[nt][1] = K32[s * SC_STRIDE + kb + 4];
            }
#pragma unroll
            for (int mt = 0; mt < 4; mt++)
#pragma unroll
                for (int nt = 0; nt < 4; nt++)
                    mma_tf32(acc[mt][nt], a[mt], bf[nt]);
        }
    }

    // exp (|logit| < ~40, no max subtraction needed), store + row partial sums
    float* dst = g_attn + ((size_t)b * TT + tBase) * TT + sBase;
    float rs0[4] = {0.f, 0.f, 0.f, 0.f};
    float rs1[4] = {0.f, 0.f, 0.f, 0.f};
#pragma unroll
    for (int mt = 0; mt < 4; mt++)
#pragma unroll
        for (int nt = 0; nt < 4; nt++) {
            float e0 = tf32_rna(__expf(acc[mt][nt][0]));
            float e1 = tf32_rna(__expf(acc[mt][nt][1]));
            float e2 = tf32_rna(__expf(acc[mt][nt][2]));
            float e3 = tf32_rna(__expf(acc[mt][nt][3]));
            int row = m0 + mt * 16 + g, col = n0 + nt * 8 + 2 * t4;
            *(float2*)(dst + (size_t)row * TT + col)       = make_float2(e0, e1);
            *(float2*)(dst + (size_t)(row + 8) * TT + col) = make_float2(e2, e3);
            rs0[mt] += e0 + e1;
            rs1[mt] += e2 + e3;
        }

#pragma unroll
    for (int mt = 0; mt < 4; mt++) {
        float v0 = rs0[mt], v1 = rs1[mt];
        v0 += __shfl_xor_sync(0xffffffffu, v0, 1);
        v0 += __shfl_xor_sync(0xffffffffu, v0, 2);
        v1 += __shfl_xor_sync(0xffffffffu, v1, 1);
        v1 += __shfl_xor_sync(0xffffffffu, v1, 2);
        if (t4 == 0) {
            rsum[m0 + mt * 16 + g][wid & 3]     = v0;
            rsum[m0 + mt * 16 + g + 8][wid & 3] = v1;
        }
    }
    __syncthreads();
    if (tid < 128) {
        float z = rsum[tid][0] + rsum[tid][1] + rsum[tid][2] + rsum[tid][3];
        g_partZ[((size_t)b * TT + tBase + tid) * 32 + blockIdx.x] = z;
    }
}

// ---------------------------------------------------------------------------
// Kernel 3: out = V @ exp(S)^T * invZ + x via mma.sync tf32.
// 3-stage cp.async ring, 1 sync/chunk. Mainloop software-pipelined at source:
// prefetch next fragment group (a[mt+1], or next-kk bf+a[0]) BEFORE issuing
// row mt's HMMAs, so LDS latency hides under tensor work.
// Accumulation order (kk -> mt -> nt) unchanged -> bitwise-identical result.
// ---------------------------------------------------------------------------
static constexpr int PV_STRIDE = 36;                        // floats per smem row
static constexpr int PV_PANEL = 128 * PV_STRIDE;            // floats per panel
static constexpr int PV_STAGE = 2 * PV_PANEL;               // A+B panels
static constexpr int SMEM_PV = 3 * PV_STAGE * 4;            // 110592 B
static constexpr int PV_NCH = TT / 32;                      // 128 chunks

__device__ __forceinline__ void pv_load_a(uint32_t* a, const uint32_t* As,
                                          int r, int kb) {
    a[0] = As[r * PV_STRIDE + kb];
    a[1] = As[(r + 8) * PV_STRIDE + kb];
    a[2] = As[r * PV_STRIDE + kb + 4];
    a[3] = As[(r + 8) * PV_STRIDE + kb + 4];
}
__device__ __forceinline__ void pv_load_b(uint32_t bf[4][2], const uint32_t* Bs,
                                          int n0, int g, int kb) {
#pragma unroll
    for (int nt = 0; nt < 4; nt++) {
        int s = n0 + nt * 8 + g;
        bf[nt][0] = Bs[s * PV_STRIDE + kb];
        bf[nt][1] = Bs[s * PV_STRIDE + kb + 4];
    }
}

__global__ __launch_bounds__(256, 2) void pv_kernel(
    const float* __restrict__ x, float* __restrict__ out)
{
    extern __shared__ float sm[];
    __shared__ float s_invZ[128];
    uint32_t sb = smem_to_u32(sm);
    int tid = threadIdx.x;
    int b = blockIdx.z, cBase = blockIdx.y << 7, tBase = blockIdx.x << 7;

    const float* va = g_v    + ((size_t)(b * CC + cBase)) * TT;
    const float* aa = g_attn + ((size_t)b * TT + tBase) * TT;

    if (tid < 128) {
        const float* pz = g_partZ + ((size_t)b * TT + tBase + tid) * 32;
        float z = 0.f;
#pragma unroll
        for (int j = 0; j < 32; j++) z += pz[j];
        s_invZ[tid] = 1.0f / z;
    }

    int lane = tid & 31, wid = tid >> 5, g = lane >> 2, t4 = lane & 3;
    int m0 = (wid >> 2) * 64, n0 = (wid & 3) * 32;

    int lr = tid >> 3, lc4 = tid & 7;

    float acc[4][4][4] = {};

    // prologue: chunks 0,1 -> stages 0,1 (one commit group each)
#pragma unroll
    for (int s = 0; s < 2; s++) {
        uint32_t Ad = sb + s * PV_STAGE * 4;
        uint32_t Bd = Ad + PV_PANEL * 4;
        const float* vs = va + s * 32;
        const float* as = aa + s * 32;
#pragma unroll
        for (int q = 0; q < 4; q++) {
            int r = lr + q * 32;
            uint32_t off = r * (PV_STRIDE * 4) + lc4 * 16;
            cp_async16(Ad + off, vs + (size_t)r * TT + lc4 * 4);
            cp_async16(Bd + off, as + (size_t)r * TT + lc4 * 4);
        }
        CP_COMMIT();
    }

    int stage = 0;                                          // = ch % 3
    for (int ch = 0; ch < PV_NCH; ch++) {
        if (ch == PV_NCH - 1) { CP_WAIT(0); } else { CP_WAIT(1); }
        __syncthreads();                                    // all reads of stage (ch-1)%3 done

        if (ch + 2 < PV_NCH) {
            int ns = stage - 1; if (ns < 0) ns += 3;        // (ch+2) % 3
            uint32_t Ad = sb + ns * PV_STAGE * 4;
            uint32_t Bd = Ad + PV_PANEL * 4;
            const float* vs = va + (ch + 2) * 32;
            const float* as = aa + (ch + 2) * 32;
#pragma unroll
            for (int q = 0; q < 4; q++) {
                int r = lr + q * 32;
                uint32_t off = r * (PV_STRIDE * 4) + lc4 * 16;
                cp_async16(Ad + off, vs + (size_t)r * TT + lc4 * 4);
                cp_async16(Bd + off, as + (size_t)r * TT + lc4 * 4);
            }
            CP_COMMIT();
        }

        const uint32_t* As = (const uint32_t*)(sm + stage * PV_STAGE);
        const uint32_t* Bs = (const uint32_t*)(sm + stage * PV_STAGE + PV_PANEL);

        // Software-pipelined mainloop: prefetch-ahead of each HMMA quartet.
        uint32_t bf[4][2], bfn[4][2];
        uint32_t a_cur[4], a_nxt[4];
        pv_load_b(bf, Bs, n0, g, t4);                       // kk=0 B fragments
        pv_load_a(a_cur, As, m0 + 0 * 16 + g, t4);          // kk=0, mt=0
#pragma unroll
        for (int kk = 0; kk < 4; kk++) {
            int kb = kk * 8 + t4;
            int kbn = kb + 8;
#pragma unroll
            for (int mt = 0; mt < 4; mt++) {
                if (mt < 3) {
                    pv_load_a(a_nxt, As, m0 + (mt + 1) * 16 + g, kb);
                } else if (kk < 3) {
                    pv_load_b(bfn, Bs, n0, g, kbn);
                    pv_load_a(a_nxt, As, m0 + 0 * 16 + g, kbn);
                }
#pragma unroll
                for (int nt = 0; nt < 4; nt++)
                    mma_tf32(acc[mt][nt], a_cur, bf[nt]);
#pragma unroll
                for (int u = 0; u < 4; u++) a_cur[u] = a_nxt[u];
            }
            if (kk < 3) {
#pragma unroll
                for (int nt = 0; nt < 4; nt++) {
                    bf[nt][0] = bfn[nt][0];
                    bf[nt][1] = bfn[nt][1];
                }
            }
        }
        stage++; if (stage == 3) stage = 0;
    }

    // epilogue: out = acc * invZ[t] + x
#pragma unroll
    for (int mt = 0; mt < 4; mt++)
#pragma unroll
        for (int nt = 0; nt < 4; nt++) {
            int nl = n0 + nt * 8 + 2 * t4;
            float z0 = s_invZ[nl], z1 = s_invZ[nl + 1];
            int crow = cBase + m0 + mt * 16 + g;
            int tcol = tBase + nl;
            size_t o0 = ((size_t)(b * CC + crow)) * TT + tcol;
            size_t o1 = ((size_t)(b * CC + crow + 8)) * TT + tcol;
            float2 x0 = *(const float2*)(x + o0);
            float2 x1 = *(const float2*)(x + o1);
            *(float2*)(out + o0) = make_float2(acc[mt][nt][0] * z0 + x0.x,
                                               acc[mt][nt][1] * z1 + x0.y);
            *(float2*)(out + o1) = make_float2(acc[mt][nt][2] * z0 + x1.x,
                                               acc[mt][nt][3] * z1 + x1.y);
        }
}

// ---------------------------------------------------------------------------
extern "C" void kernel_launch(void* const* d_in, const int* in_sizes, int n_in,
                              void* d_out, int out_size)
{
    const float* x  = (const float*)d_in[0];
    const float* Wq = (const float*)d_in[1];
    const float* bq = (const float*)d_in[2];
    const float* Wk = (const float*)d_in[3];
    const float* bk = (const float*)d_in[4];
    const float* Wv = (const float*)d_in[5];
    const float* bv = (const float*)d_in[6];
    float* out = (float*)d_out;

    static bool attr_done = false;
    if (!attr_done) {
        cudaFuncSetAttribute(proj_kernel,   cudaFuncAttributeMaxDynamicSharedMemorySize, SMEM_PJ);
        cudaFuncSetAttribute(scores_kernel, cudaFuncAttributeMaxDynamicSharedMemorySize, SMEM_SC);
        cudaFuncSetAttribute(pv_kernel,     cudaFuncAttributeMaxDynamicSharedMemorySize, SMEM_PV);
        attr_done = true;
    }

    wsplit_kernel<<<384, 256>>>(Wq, bq, Wk, bk, Wv, bv);
    proj_kernel<<<dim3(TT / 128, 3, BB), 256, SMEM_PJ>>>(x);
    scores_kernel<<<dim3(TT / 128, TT / 128, BB), 256, SMEM_SC>>>();
    pv_kernel<<<dim3(TT / 128, CC / 128, BB), 256, SMEM_PV>>>(x, out);
}

// round 15
// speedup vs baseline: 1.2954x; 1.2954x over previous
#include <cuda_runtime.h>
#include <cuda_fp16.h>
#include <cstdint>

#define BB 4
#define CC 256
#define TT 4096
#define CQ 32

// ---------------------------------------------------------------------------
// Scratch (allocation-free: __device__ globals)
// ---------------------------------------------------------------------------
__device__ float  g_qs[(size_t)BB * TT * 64];    // [B*T][64]: 0-31 q_hi(tf32), 32-63 q_lo
__device__ float  g_ks[(size_t)BB * TT * 64];    // [B*T][64]: k_hi | k_lo
__device__ __half g_v[(size_t)BB * CC * TT];     // [B, C, T], fp16
__device__ __half g_attn[(size_t)BB * TT * TT];  // [B, T, T]: fp16(exp(S-shift_t)) (128 MB)
__device__ float  g_partZ[(size_t)BB * TT * 32]; // per-row per-s-tile partial sums
__device__ float  g_Whi[384 * 256];              // stacked W (q|k|v|pad), tf32 hi
__device__ float  g_Wlo[384 * 256];              // residual lo (rows 320-383 zero)
__device__ float  g_bias[384];

// shift = 4.3 * ||q||: row max-z ~ 4.08 +- 0.35 => dominant weights stay in
// fp16 NORMAL range (>= e^{-0.6 sigma}), overflow needs z > 4.3 + 11/sigma.
#define SHIFT_MULT 4.3f

// ---------------------------------------------------------------------------
// Helpers (target-agnostic PTX only: mma.sync + cp.async, sm_80+ baseline)
// ---------------------------------------------------------------------------
__device__ __forceinline__ uint32_t smem_to_u32(const void* p) {
    uint32_t a;
    asm("{ .reg .u64 t; cvta.to.shared.u64 t, %1; cvt.u32.u64 %0, t; }" : "=r"(a) : "l"(p));
    return a;
}
__device__ __forceinline__ float tf32_rna(float x) {
    float r;
    asm("cvt.rna.tf32.f32 %0, %1;" : "=f"(r) : "f"(x));
    return r;
}
__device__ __forceinline__ void mma_tf32(float* c, const uint32_t* a, const uint32_t* b) {
    asm volatile(
        "mma.sync.aligned.m16n8k8.row.col.f32.tf32.tf32.f32 "
        "{%0,%1,%2,%3}, {%4,%5,%6,%7}, {%8,%9}, {%0,%1,%2,%3};"
        : "+f"(c[0]), "+f"(c[1]), "+f"(c[2]), "+f"(c[3])
        : "r"(a[0]), "r"(a[1]), "r"(a[2]), "r"(a[3]), "r"(b[0]), "r"(b[1]));
}
__device__ __forceinline__ void mma_f16(float* c, const uint32_t* a, const uint32_t* b) {
    asm volatile(
        "mma.sync.aligned.m16n8k16.row.col.f32.f16.f16.f32 "
        "{%0,%1,%2,%3}, {%4,%5,%6,%7}, {%8,%9}, {%0,%1,%2,%3};"
        : "+f"(c[0]), "+f"(c[1]), "+f"(c[2]), "+f"(c[3])
        : "r"(a[0]), "r"(a[1]), "r"(a[2]), "r"(a[3]), "r"(b[0]), "r"(b[1]));
}
__device__ __forceinline__ void cp_async16(uint32_t dst, const void* src) {
    asm volatile("cp.async.cg.shared.global [%0], [%1], 16;" :: "r"(dst), "l"(src));
}
#define CP_COMMIT() asm volatile("cp.async.commit_group;" ::: "memory")
#define CP_WAIT(n)  asm volatile("cp.async.wait_group %0;" :: "n"(n) : "memory")

// ---------------------------------------------------------------------------
// Kernel 0: split stacked weights into tf32 hi/lo + gather bias.
// ---------------------------------------------------------------------------
__global__ __launch_bounds__(256) void wsplit_kernel(
    const float* __restrict__ Wq, const float* __restrict__ bq,
    const float* __restrict__ Wk, const float* __restrict__ bk,
    const float* __restrict__ Wv, const float* __restrict__ bv)
{
    int i = blockIdx.x * 256 + threadIdx.x;                 // < 384*256
    int row = i >> 8, c = i & 255;
    float w = 0.f;
    if (row < 32)       w = Wq[row * 256 + c];
    else if (row < 64)  w = Wk[(row - 32) * 256 + c];
    else if (row < 320) w = Wv[(row - 64) * 256 + c];
    float hi = tf32_rna(w);
    g_Whi[i] = hi;
    g_Wlo[i] = w - hi;
    if (i < 384) {
        float bb = 0.f;
        if (i < 32)       bb = bq[i];
        else if (i < 64)  bb = bk[i - 32];
        else if (i < 320) bb = bv[i - 64];
        g_bias[i] = bb;
    }
}

// ---------------------------------------------------------------------------
// Kernel 1: projections via mma.sync tf32. v stored fp16.
// ---------------------------------------------------------------------------
static constexpr int PJ_WS = 36;                            // W smem k-stride
static constexpr int PJ_XS = 132;                            // X smem t-stride
static constexpr int PJ_WH = 0;                             // float offsets
static constexpr int PJ_WL = PJ_WH + 128 * PJ_WS;
static constexpr int PJ_XH = PJ_WL + 128 * PJ_WS;
static constexpr int PJ_XL = PJ_XH + 32 * PJ_XS;
static constexpr int SMEM_PJ = (PJ_XL + 32 * PJ_XS) * 4;    // 70656 B

__global__ __launch_bounds__(256, 2) void proj_kernel(const float* __restrict__ x)
{
    extern __shared__ float sm[];
    int tid = threadIdx.x;
    int b = blockIdx.z, mBase = blockIdx.y << 7, tBase = blockIdx.x << 7;
    int passes = (blockIdx.y == 0) ? 3 : 1;

    int lane = tid & 31, wid = tid >> 5, g = lane >> 2, t4 = lane & 3;
    int m0 = (wid >> 2) * 64, n0 = (wid & 3) * 32;

    float acc[4][4][4] = {};

    for (int ch = 0; ch < 8; ch++) {
        __syncthreads();
        for (int i = tid; i < 1024; i += 256) {
            int r = i >> 3, c4 = i & 7;
            size_t gsrc = (size_t)(mBase + r) * 256 + ch * 32 + c4 * 4;
            *(float4*)(sm + PJ_WH + r * PJ_WS + c4 * 4) = *(const float4*)(g_Whi + gsrc);
            *(float4*)(sm + PJ_WL + r * PJ_WS + c4 * 4) = *(const float4*)(g_Wlo + gsrc);
        }
        for (int i = tid; i < 1024; i += 256) {
            int cl = i >> 5, tl = i & 31;
            float4 xv = *(const float4*)(x + ((size_t)(b * CC + ch * 32 + cl)) * TT + tBase + tl * 4);
            float4 h = make_float4(tf32_rna(xv.x), tf32_rna(xv.y), tf32_rna(xv.z), tf32_rna(xv.w));
            float4 l = make_float4(xv.x - h.x, xv.y - h.y, xv.z - h.z, xv.w - h.w);
            *(float4*)(sm + PJ_XH + cl * PJ_XS + tl * 4) = h;
            *(float4*)(sm + PJ_XL + cl * PJ_XS + tl * 4) = l;
        }
        __syncthreads();

        const uint32_t* Wh = (const uint32_t*)(sm + PJ_WH);
        const uint32_t* Wl = (const uint32_t*)(sm + PJ_WL);
        const uint32_t* Xh = (const uint32_t*)(sm + PJ_XH);
        const uint32_t* Xl = (const uint32_t*)(sm + PJ_XL);

        for (int p = 0; p < passes; p++) {
            const uint32_t* Aw = (p == 2) ? Wl : Wh;
            const uint32_t* Bx = (p == 1) ? Xl : Xh;
#pragma unroll
            for (int kk = 0; kk < 4; kk++) {
                int ka = kk * 8 + t4;
                uint32_t a[4][4], bf[4][2];
#pragma unroll
                for (int mt = 0; mt < 4; mt++) {
                    int r = m0 + mt * 16 + g;
                    a[mt][0] = Aw[r * PJ_WS + ka];
                    a[mt][1] = Aw[(r + 8) * PJ_WS + ka];
                    a[mt][2] = Aw[r * PJ_WS + ka + 4];
                    a[mt][3] = Aw[(r + 8) * PJ_WS + ka + 4];
                }
#pragma unroll
                for (int nt = 0; nt < 4; nt++) {
                    int s = n0 + nt * 8 + g;
                    bf[nt][0] = Bx[ka * PJ_XS + s];
                    bf[nt][1] = Bx[(ka + 4) * PJ_XS + s];
                }
#pragma unroll
                for (int mt = 0; mt < 4; mt++)
#pragma unroll
                    for (int nt = 0; nt < 4; nt++)
                        mma_tf32(acc[mt][nt], a[mt], bf[nt]);
            }
        }
    }

    // Epilogue: q/k -> tf32 split; v -> fp16. Rows >= 320 are padding.
#pragma unroll
    for (int mt = 0; mt < 4; mt++)
#pragma unroll
        for (int nt = 0; nt < 4; nt++) {
#pragma unroll
            for (int half = 0; half < 2; half++) {
                int grow = mBase + m0 + mt * 16 + g + half * 8;
                int tcol = tBase + n0 + nt * 8 + 2 * t4;
                float v0 = acc[mt][nt][half * 2 + 0] + g_bias[grow];
                float v1 = acc[mt][nt][half * 2 + 1] + g_bias[grow];
                if (grow < 64) {
                    float* base = (grow < 32) ? g_qs : g_ks;
                    int r = grow & 31;
                    float h0 = tf32_rna(v0), h1 = tf32_rna(v1);
                    size_t r0 = ((size_t)b * TT + tcol) * 64;
                    size_t r1 = ((size_t)b * TT + tcol + 1) * 64;
                    base[r0 + r] = h0; base[r0 + 32 + r] = v0 - h0;
                    base[r1 + r] = h1; base[r1 + 32 + r] = v1 - h1;
                } else if (grow < 320) {
                    size_t o = ((size_t)(b * CC + grow - 64)) * TT + tcol;
                    *(__half2*)(g_v + o) = __floats2half2_rn(v0, v1);
                }
            }
        }
}

// ---------------------------------------------------------------------------
// Kernel 2: scores + exp, mma.sync tf32 (3-pass split: hh, hl, lh).
// PER-ROW shift = 4.3*||q_t|| (bitwise-identical across all s-blocks of a
// tBase). Weights stored fp16; partZ sums the fp16-ROUNDED values so the
// numerator (pv) and denominator use identical quantized weights.
// Clamp at 60000 (graceful; clamped value summed consistently).
// ---------------------------------------------------------------------------
static constexpr int SC_STRIDE = 68;
static constexpr int SMEM_SC = 2 * 128 * SC_STRIDE * 4;     // 69632 B

__global__ __launch_bounds__(256, 2) void scores_kernel()
{
    extern __shared__ float sm[];
    __shared__ float rsum[128][4];
    __shared__ float s_shift[128];
    float* Qs = sm;
    float* Ks = sm + 128 * SC_STRIDE;
    int tid = threadIdx.x;
    int b = blockIdx.z, tBase = blockIdx.y << 7, sBase = blockIdx.x << 7;

    const float* qsrc = g_qs + ((size_t)b * TT + tBase) * 64;
    const float* ksrc = g_ks + ((size_t)b * TT + sBase) * 64;
    for (int i = tid; i < 2048; i += 256) {
        int r = i >> 4, c4 = i & 15;
        *(float4*)(Qs + r * SC_STRIDE + c4 * 4) = *(const float4*)(qsrc + r * 64 + c4 * 4);
        *(float4*)(Ks + r * SC_STRIDE + c4 * 4) = *(const float4*)(ksrc + r * 64 + c4 * 4);
    }
    __syncthreads();

    // Per-row shift from ||q||; identical (bitwise) in every block of this tBase.
    if (tid < 128) {
        const float* qr = Qs + tid * SC_STRIDE;
        float ss = 0.f;
#pragma unroll
        for (int d = 0; d < 32; d++) {
            float qv = qr[d] + qr[32 + d];
            ss += qv * qv;
        }
        s_shift[tid] = SHIFT_MULT * sqrtf(ss);
    }
    __syncthreads();

    int lane = tid & 31, wid = tid >> 5, g = lane >> 2, t4 = lane & 3;
    int m0 = (wid >> 2) * 64, n0 = (wid & 3) * 32;

    float acc[4][4][4] = {};
    const uint32_t* Q32 = (const uint32_t*)Qs;
    const uint32_t* K32 = (const uint32_t*)Ks;

    const int amap[3] = {0, 0, 32};                         // (qh,kh)(qh,kl)(ql,kh)
    const int bmap[3] = {0, 32, 0};
#pragma unroll
    for (int p = 0; p < 3; p++) {
#pragma unroll
        for (int kk = 0; kk < 4; kk++) {
            int ka = amap[p] + kk * 8 + t4;
            int kb = bmap[p] + kk * 8 + t4;
            uint32_t a[4][4], bf[4][2];
#pragma unroll
            for (int mt = 0; mt < 4; mt++) {
                int r = m0 + mt * 16 + g;
                a[mt][0] = Q32[r * SC_STRIDE + ka];
                a[mt][1] = Q32[(r + 8) * SC_STRIDE + ka];
                a[mt][2] = Q32[r * SC_STRIDE + ka + 4];
                a[mt][3] = Q32[(r + 8) * SC_STRIDE + ka + 4];
            }
#pragma unroll
            for (int nt = 0; nt < 4; nt++) {
                int s = n0 + nt * 8 + g;
                bf[nt][0] = K32[s * SC_STRIDE + kb];
                bf[nt][1] = K32[s * SC_STRIDE + kb + 4];
            }
#pragma unroll
            for (int mt = 0; mt < 4; mt++)
#pragma unroll
                for (int nt = 0; nt < 4; nt++)
                    mma_tf32(acc[mt][nt], a[mt], bf[nt]);
        }
    }

    // exp(S - shift_row), clamp, fp16-round; sum the ROUNDED values.
    __half* dst = g_attn + ((size_t)b * TT + tBase) * TT + sBase;
    float rs0[4] = {0.f, 0.f, 0.f, 0.f};
    float rs1[4] = {0.f, 0.f, 0.f, 0.f};
#pragma unroll
    for (int mt = 0; mt < 4; mt++) {
        int row = m0 + mt * 16 + g;
        float sh0 = s_shift[row], sh1 = s_shift[row + 8];
#pragma unroll
        for (int nt = 0; nt < 4; nt++) {
            float e0 = fminf(__expf(acc[mt][nt][0] - sh0), 60000.f);
            float e1 = fminf(__expf(acc[mt][nt][1] - sh0), 60000.f);
            float e2 = fminf(__expf(acc[mt][nt][2] - sh1), 60000.f);
            float e3 = fminf(__expf(acc[mt][nt][3] - sh1), 60000.f);
            __half2 h01 = __floats2half2_rn(e0, e1);
            __half2 h23 = __floats2half2_rn(e2, e3);
            int col = n0 + nt * 8 + 2 * t4;
            *(__half2*)(dst + (size_t)row * TT + col)       = h01;
            *(__half2*)(dst + (size_t)(row + 8) * TT + col) = h23;
            rs0[mt] += __half2float(__low2half(h01)) + __half2float(__high2half(h01));
            rs1[mt] += __half2float(__low2half(h23)) + __half2float(__high2half(h23));
        }
    }

#pragma unroll
    for (int mt = 0; mt < 4; mt++) {
        float v0 = rs0[mt], v1 = rs1[mt];
        v0 += __shfl_xor_sync(0xffffffffu, v0, 1);
        v0 += __shfl_xor_sync(0xffffffffu, v0, 2);
        v1 += __shfl_xor_sync(0xffffffffu, v1, 1);
        v1 += __shfl_xor_sync(0xffffffffu, v1, 2);
        if (t4 == 0) {
            rsum[m0 + mt * 16 + g][wid & 3]     = v0;
            rsum[m0 + mt * 16 + g + 8][wid & 3] = v1;
        }
    }
    __syncthreads();
    if (tid < 128) {
        float z = rsum[tid][0] + rsum[tid][1] + rsum[tid][2] + rsum[tid][3];
        g_partZ[((size_t)b * TT + tBase + tid) * 32 + blockIdx.x] = z;
    }
}

// ---------------------------------------------------------------------------
// Kernel 3: out = V @ w^T * invZ + x via mma.sync f16 (m16n8k16).
// HMMA count and fragment LDS bytes HALVED vs tf32.
// 3-stage cp.async ring, 1 sync/chunk (round-9 proven structure).
// Smem row = 32 halves + pad to 40 (word stride 20: g*20+t4 bank-clean).
// ---------------------------------------------------------------------------
static constexpr int PV_ST_H  = 40;                         // halves per smem row
static constexpr int PV_PAN_H = 128 * PV_ST_H;              // halves per panel
static constexpr int PV_STG_H = 2 * PV_PAN_H;               // A+B panels
static constexpr int SMEM_PV  = 3 * PV_STG_H * 2;           // 61440 B
static constexpr int PV_NCH   = TT / 32;                    // 128 chunks

__global__ __launch_bounds__(256, 2) void pv_kernel(
    const float* __restrict__ x, float* __restrict__ out)
{
    extern __shared__ __half smh[];
    __shared__ float s_invZ[128];
    uint32_t sb = smem_to_u32(smh);
    int tid = threadIdx.x;
    int b = blockIdx.z, cBase = blockIdx.y << 7, tBase = blockIdx.x << 7;

    const __half* va = g_v    + ((size_t)(b * CC + cBase)) * TT;
    const __half* aa = g_attn + ((size_t)b * TT + tBase) * TT;

    if (tid < 128) {
        const float* pz = g_partZ + ((size_t)b * TT + tBase + tid) * 32;
        float z = 0.f;
#pragma unroll
        for (int j = 0; j < 32; j++) z += pz[j];
        s_invZ[tid] = 1.0f / z;
    }

    int lane = tid & 31, wid = tid >> 5, g = lane >> 2, t4 = lane & 3;
    int m0 = (wid >> 2) * 64, n0 = (wid & 3) * 32;

    // cp.async mapping: 512 16B-granules per panel (128 rows x 4), 2 iters/thread
    int lr = tid >> 2, lc8 = tid & 3;                       // rows 0..63, granule 0..3

    float acc[4][4][4] = {};

    // prologue: chunks 0,1 -> stages 0,1
#pragma unroll
    for (int s = 0; s < 2; s++) {
        uint32_t Ad = sb + s * PV_STG_H * 2;
        uint32_t Bd = Ad + PV_PAN_H * 2;
        const __half* vs = va + s * 32;
        const __half* as = aa + s * 32;
#pragma unroll
        for (int q = 0; q < 2; q++) {
            int r = lr + q * 64;
            uint32_t off = r * (PV_ST_H * 2) + lc8 * 16;
            cp_async16(Ad + off, vs + (size_t)r * TT + lc8 * 8);
            cp_async16(Bd + off, as + (size_t)r * TT + lc8 * 8);
        }
        CP_COMMIT();
    }

    int stage = 0;                                          // = ch % 3
    for (int ch = 0; ch < PV_NCH; ch++) {
        if (ch == PV_NCH - 1) { CP_WAIT(0); } else { CP_WAIT(1); }
        __syncthreads();                                    // all reads of stage (ch-1)%3 done

        if (ch + 2 < PV_NCH) {
            int ns = stage - 1; if (ns < 0) ns += 3;        // (ch+2) % 3
            uint32_t Ad = sb + ns * PV_STG_H * 2;
            uint32_t Bd = Ad + PV_PAN_H * 2;
            const __half* vs = va + (ch + 2) * 32;
            const __half* as = aa + (ch + 2) * 32;
#pragma unroll
            for (int q = 0; q < 2; q++) {
                int r = lr + q * 64;
                uint32_t off = r * (PV_ST_H * 2) + lc8 * 16;
                cp_async16(Ad + off, vs + (size_t)r * TT + lc8 * 8);
                cp_async16(Bd + off, as + (size_t)r * TT + lc8 * 8);
            }
            CP_COMMIT();
        }

        // b32 view: row stride = 20 words; k-step = 8 words (16 halves)
        const uint32_t* As = (const uint32_t*)(smh + stage * PV_STG_H);
        const uint32_t* Bs = (const uint32_t*)(smh + stage * PV_STG_H + PV_PAN_H);
#pragma unroll
        for (int ks = 0; ks < 2; ks++) {
            int kb = ks * 8 + t4;
            uint32_t a[4][4], bf[4][2];
#pragma unroll
            for (int mt = 0; mt < 4; mt++) {
                int r = m0 + mt * 16 + g;
                a[mt][0] = As[r * 20 + kb];
                a[mt][1] = As[(r + 8) * 20 + kb];
                a[mt][2] = As[r * 20 + kb + 4];
                a[mt][3] = As[(r + 8) * 20 + kb + 4];
            }
#pragma unroll
            for (int nt = 0; nt < 4; nt++) {
                int s = n0 + nt * 8 + g;
                bf[nt][0] = Bs[s * 20 + kb];
                bf[nt][1] = Bs[s * 20 + kb + 4];
            }
#pragma unroll
            for (int mt = 0; mt < 4; mt++)
#pragma unroll
                for (int nt = 0; nt < 4; nt++)
                    mma_f16(acc[mt][nt], a[mt], bf[nt]);
        }
        stage++; if (stage == 3) stage = 0;
    }

    // epilogue: out = acc * invZ[t] + x
#pragma unroll
    for (int mt = 0; mt < 4; mt++)
#pragma unroll
        for (int nt = 0; nt < 4; nt++) {
            int nl = n0 + nt * 8 + 2 * t4;
            float z0 = s_invZ[nl], z1 = s_invZ[nl + 1];
            int crow = cBase + m0 + mt * 16 + g;
            int tcol = tBase + nl;
            size_t o0 = ((size_t)(b * CC + crow)) * TT + tcol;
            size_t o1 = ((size_t)(b * CC + crow + 8)) * TT + tcol;
            float2 x0 = *(const float2*)(x + o0);
            float2 x1 = *(const float2*)(x + o1);
            *(float2*)(out + o0) = make_float2(acc[mt][nt][0] * z0 + x0.x,
                                               acc[mt][nt][1] * z1 + x0.y);
            *(float2*)(out + o1) = make_float2(acc[mt][nt][2] * z0 + x1.x,
                                               acc[mt][nt][3] * z1 + x1.y);
        }
}

// ---------------------------------------------------------------------------
extern "C" void kernel_launch(void* const* d_in, const int* in_sizes, int n_in,
                              void* d_out, int out_size)
{
    const float* x  = (const float*)d_in[0];
    const float* Wq = (const float*)d_in[1];
    const float* bq = (const float*)d_in[2];
    const float* Wk = (const float*)d_in[3];
    const float* bk = (const float*)d_in[4];
    const float* Wv = (const float*)d_in[5];
    const float* bv = (const float*)d_in[6];
    float* out = (float*)d_out;

    static bool attr_done = false;
    if (!attr_done) {
        cudaFuncSetAttribute(proj_kernel,   cudaFuncAttributeMaxDynamicSharedMemorySize, SMEM_PJ);
        cudaFuncSetAttribute(scores_kernel, cudaFuncAttributeMaxDynamicSharedMemorySize, SMEM_SC);
        cudaFuncSetAttribute(pv_kernel,     cudaFuncAttributeMaxDynamicSharedMemorySize, SMEM_PV);
        attr_done = true;
    }

    wsplit_kernel<<<384, 256>>>(Wq, bq, Wk, bk, Wv, bv);
    proj_kernel<<<dim3(TT / 128, 3, BB), 256, SMEM_PJ>>>(x);
    scores_kernel<<<dim3(TT / 128, TT / 128, BB), 256, SMEM_SC>>>();
    pv_kernel<<<dim3(TT / 128, CC / 128, BB), 256, SMEM_PV>>>(x, out);
}